// round 17
// baseline (speedup 1.0000x reference)
#include <cuda_runtime.h>
#include <cuda_bf16.h>
#include <float.h>
#include <math.h>
#include <stdint.h>

// Problem constants (from reference)
#define H 512
#define W 512
#define PSIZE 4
#define NEUR 32
#define TOPK 4
#define S2 16
#define NH 509            // (512 - 3) / 1
#define NW 509
#define NZ (NH * NW)      // 259081
#define EPSV 1e-8f
// near-tie window: >> fast-vs-exact pre delta (~1e-6), << typical 4th/5th
// gap (~6e-3) -> exact path runs on a few % of rows
#define TIE_TAU 5e-4f

#define WARPS_PER_BLOCK 8
#define NBUF 3             // triple buffer -> 2 tiles of lookahead
#define CHUNK 16           // z per warp

// R17: R16's 2-buffer pipeline had only ONE tile of lookahead -- the warp
// computes ~350cyc then stalls the rest of the ~800cyc DRAM round trip, so
// in-flight bytes (and DRAM=57%) never moved vs R13. Triple buffering gives
// 2 tiles (4KB/warp) of lookahead at ~90% duty; 48KB static smem still
// permits 4 blocks/SM; CHUNK=16 halves pipeline fill/drain overhead; the
// address math is slimmed to cut regs (58 -> ~48) and restore occupancy.
// Numerics byte-identical to R16 (same slots, fast path, REDUX top-4,
// exact XLA-emulation rescue).
__device__ __forceinline__ void cp16(unsigned int dst_smem, const void* src) {
    asm volatile("cp.async.cg.shared.global [%0], [%1], 16;"
                 :: "r"(dst_smem), "l"(src));
}
__device__ __forceinline__ void cp_commit() {
    asm volatile("cp.async.commit_group;" ::: "memory");
}
__device__ __forceinline__ void cp_wait2() {
    asm volatile("cp.async.wait_group 2;" ::: "memory");
}

__device__ __forceinline__ float top4_threshold(unsigned mybits, int lane)
{
    const unsigned FULL = 0xFFFFFFFFu;
    unsigned active = mybits;   // pre >= 0 always -> float order == uint order
    unsigned thrbits = 0;
#pragma unroll
    for (int k = 0; k < TOPK; k++) {
        thrbits = __reduce_max_sync(FULL, active);
        unsigned ball = __ballot_sync(FULL, active == thrbits);
        if (lane == (int)__ffs(ball) - 1) active = 0u;
    }
    return __uint_as_float(thrbits);
}

__global__ __launch_bounds__(256)
void topk_layer2d_kernel(const float* __restrict__ x,
                         const float* __restrict__ Wz,
                         float* __restrict__ out)
{
    // NBUF buffers x 2KB per warp = 48KB per block (static smem limit)
    __shared__ float4 sw[WARPS_PER_BLOCK][NBUF][NEUR * 4];

    const int lane = threadIdx.x & 31;
    const int warp = threadIdx.x >> 5;
    const int gw   = blockIdx.x * WARPS_PER_BLOCK + warp;
    const int z0   = gw * CHUNK;
    if (z0 >= NZ) return;
    const int nzw = min(CHUNK, NZ - z0);   // warp-uniform

    // per-lane swizzled slot byte-offsets: j=i*32+lane, n=j>>2, q=j&3,
    // slot = n*4 + ((q + (n>>1)) & 3)
    unsigned int slotoff[4];
#pragma unroll
    for (int i = 0; i < 4; i++) {
        const int j = i * 32 + lane;
        const int n = j >> 2, q = j & 3;
        slotoff[i] = (unsigned int)(n * 4 + ((q + (n >> 1)) & 3)) * 16u;
    }
    const unsigned int smbase =
        (unsigned int)__cvta_generic_to_shared(&sw[warp][0][0]);

    const float4* wbase =
        reinterpret_cast<const float4*>(Wz) + (size_t)z0 * (NEUR * 4);

    // ---- prologue: stream tiles 0 and 1 ----
#pragma unroll
    for (int s = 0; s < NBUF - 1; s++) {
        if (s < nzw) {
            const float4* src = wbase + (size_t)s * (NEUR * 4);
            const unsigned int b = smbase + (unsigned int)s * 2048u;
#pragma unroll
            for (int i = 0; i < 4; i++)
                cp16(b + slotoff[i], src + (i * 32 + lane));
        }
        cp_commit();
    }

    const unsigned FULL = 0xFFFFFFFFu;
    int buf = 0, pbuf = NBUF - 1;          // compute buffer / prefetch buffer

    for (int t = 0; t < nzw; t++) {        // warp-uniform trip count
        const int z = z0 + t;

        // ---- prefetch tile t+2 into the just-freed buffer ----
        if (t + NBUF - 1 < nzw) {
            const float4* nsrc = wbase + (size_t)(t + NBUF - 1) * (NEUR * 4);
            const unsigned int b = smbase + (unsigned int)pbuf * 2048u;
#pragma unroll
            for (int i = 0; i < 4; i++)
                cp16(b + slotoff[i], nsrc + (i * 32 + lane));
        }
        cp_commit();
        cp_wait2();     // <=2 groups pending -> tile t's copies complete
        __syncwarp();   // publish all lanes' async writes warp-wide

        // ---- gather own neuron row (conflict-free LDS.128) ----
        float w[S2];
        {
            const int rot = (lane >> 1) & 3;
#pragma unroll
            for (int q = 0; q < 4; q++) {
                float4 v = sw[warp][buf][lane * 4 + ((q + rot) & 3)];
                w[q*4+0] = v.x; w[q*4+1] = v.y; w[q*4+2] = v.z; w[q*4+3] = v.w;
            }
        }
        __syncwarp();   // all lanes done reading before this buffer refills

        const int r = z / NW;
        const int c = z - r * NW;

        // ---- patch (uniform-address broadcast loads, L1-resident) ----
        float p[S2];
#pragma unroll
        for (int a = 0; a < PSIZE; a++)
#pragma unroll
            for (int b2 = 0; b2 < PSIZE; b2++)
                p[a * PSIZE + b2] = __ldg(&x[(r + a) * W + (c + b2)]);

        // ================= FAST PATH =================
        float pacc = 0.f, wacc = 0.f, dp = 0.f;
#pragma unroll
        for (int d = 0; d < S2; d++) {
            pacc = fmaf(p[d], p[d], pacc);
            wacc = fmaf(w[d], w[d], wacc);
            dp   = fmaf(w[d], p[d], dp);
        }
        const float den = (sqrtf(wacc) + EPSV) * (sqrtf(pacc) + EPSV);
        float pre = __fdividef(dp, den);

        float thr = top4_threshold(__float_as_uint(pre), lane);

        // ============ EXACT RESCUE (rare, warp-uniform) ============
        // Risky iff MORE than 4 lanes are candidates at thr - tau (the
        // 4th/5th gap is below tau). Exactly 4 -> gap > tau -> safe.
        const unsigned nearMask = __ballot_sync(FULL, pre >= thr - TIE_TAU);
        if (__popc(nearMask) > 4) {
            // patch norm: rounded square + sequential rounded adds, ascending
            float pa = 0.f;
#pragma unroll
            for (int d = 0; d < S2; d++)
                pa = __fadd_rn(pa, __fmul_rn(p[d], p[d]));
            const float pden = __fadd_rn(__fsqrt_rn(pa), EPSV);
            // pn is warp-uniform: lane d (<16) does element d's rounded divide
            const float pn_mine = (lane < S2) ? __fdiv_rn(p[lane], pden) : 0.f;

            float wa = 0.f;
#pragma unroll
            for (int d = 0; d < S2; d++)
                wa = __fadd_rn(wa, __fmul_rn(w[d], w[d]));
            const float wden = __fadd_rn(__fsqrt_rn(wa), EPSV);

            // pre = reduce(mul): rounded mul, rounded add, ascending (no FMA)
            float acc = 0.f;
#pragma unroll
            for (int d = 0; d < S2; d++) {
                const float pn_d = __shfl_sync(FULL, pn_mine, d);
                const float wn_d = __fdiv_rn(w[d], wden);
                acc = __fadd_rn(acc, __fmul_rn(wn_d, pn_d));
            }
            pre = acc;   // exact values for this row (matches R6 bit-for-bit)
            thr = top4_threshold(__float_as_uint(pre), lane);
        }

        // coalesced 128B store per warp
        out[(size_t)z * NEUR + lane] = (pre >= thr) ? pre : 0.f;

        // rotate ring indices
        buf  = (buf  + 1 == NBUF) ? 0 : buf + 1;
        pbuf = (pbuf + 1 == NBUF) ? 0 : pbuf + 1;
    }
}

extern "C" void kernel_launch(void* const* d_in, const int* in_sizes, int n_in,
                              void* d_out, int out_size)
{
    const float* x  = (const float*)d_in[0];   // (512, 512) fp32
    const float* Wz = (const float*)d_in[1];   // (NZ, 32, 16) fp32
    float* out = (float*)d_out;                // (NZ, 32) fp32

    const int z_per_block = WARPS_PER_BLOCK * CHUNK;
    const int blocks = (NZ + z_per_block - 1) / z_per_block;
    topk_layer2d_kernel<<<blocks, WARPS_PER_BLOCK * 32>>>(x, Wz, out);
}